// round 2
// baseline (speedup 1.0000x reference)
#include <cuda_runtime.h>

// DynamicPatching: B=32, C=64, T=8192, S=64 segments.
// out[b][s][c][p] = (p < end[b,s]-start[b,s]) ? tensor[b][c][start[b,s]+p] : 0
// Output shape (B, S, C, max_len), row-major. Pure HBM-streaming gather.

#define PB 32
#define PC 64
#define PT 8192
#define PS 64

__global__ void __launch_bounds__(256, 8)
dynamic_patching_kernel(const float* __restrict__ tensor,
                        const int*   __restrict__ cps,   // (B, S+1) int32
                        float*       __restrict__ out,
                        int max_len)
{
    // One block per (b, s) segment.
    const int bs = blockIdx.x;          // 0 .. B*S-1
    const int b  = bs >> 6;             // / PS
    const int s  = bs & (PS - 1);       // % PS

    const int start = cps[b * (PS + 1) + s];
    const int end   = cps[b * (PS + 1) + s + 1];
    const int len   = end - start;      // 0 <= len <= max_len, start+len <= T

    const float* __restrict__ src = tensor + ((long long)b * PC) * PT + start;
    float*       __restrict__ dst = out    + ((long long)bs * PC) * (long long)max_len;

    // Threads cover p (contiguous in both src and dst -> coalesced both ways).
    // Unroll channels by 4 to keep >=4 independent LDGs in flight per thread.
    for (int p = threadIdx.x; p < max_len; p += blockDim.x) {
        const bool in = (p < len);
        #pragma unroll 1
        for (int c0 = 0; c0 < PC; c0 += 4) {
            float v0 = 0.f, v1 = 0.f, v2 = 0.f, v3 = 0.f;
            if (in) {
                v0 = src[(long long)(c0 + 0) * PT + p];
                v1 = src[(long long)(c0 + 1) * PT + p];
                v2 = src[(long long)(c0 + 2) * PT + p];
                v3 = src[(long long)(c0 + 3) * PT + p];
            }
            dst[(long long)(c0 + 0) * max_len + p] = v0;
            dst[(long long)(c0 + 1) * max_len + p] = v1;
            dst[(long long)(c0 + 2) * max_len + p] = v2;
            dst[(long long)(c0 + 3) * max_len + p] = v3;
        }
    }
}

extern "C" void kernel_launch(void* const* d_in, const int* in_sizes, int n_in,
                              void* d_out, int out_size)
{
    const float* tensor = (const float*)d_in[0];
    const int*   cps    = (const int*)d_in[1];   // change_points, int32 (JAX default x64=off)
    float*       out    = (float*)d_out;

    // out_size = B * S * C * max_len
    const int max_len = out_size / (PB * PS * PC);

    dynamic_patching_kernel<<<PB * PS, 256>>>(tensor, cps, out, max_len);
}

// round 3
// speedup vs baseline: 1.1454x; 1.1454x over previous
#include <cuda_runtime.h>

// DynamicPatching: B=32, C=64, T=8192, S=64.
// out[b][s][c][p] = (p < len_bs) ? tensor[b][c][start_bs + p] : 0
// Output (B, S, C, max_len) row-major. HBM-streaming; vectorized STG.128 body
// with per-row alignment fixup, predicated scalar loads (pad region = pure stores).

#define PB 32
#define PC 64
#define PT 8192
#define PS 64

__global__ void __launch_bounds__(256)
dynamic_patching_kernel(const float* __restrict__ tensor,
                        const int*   __restrict__ cps,   // (B, S+1) int32
                        float*       __restrict__ out,
                        int max_len)
{
    // 2 blocks per (b,s): each block covers 32 of the 64 channels.
    const int bs   = blockIdx.x >> 1;
    const int half = blockIdx.x & 1;
    const int b    = bs >> 6;            // / PS
    const int s    = bs & (PS - 1);      // % PS

    const int start = __ldg(cps + b * (PS + 1) + s);
    const int len   = __ldg(cps + b * (PS + 1) + s + 1) - start;

    const float* __restrict__ src_base = tensor + ((size_t)b * PC) * PT + start;
    const long long out_base = (long long)bs * PC * (long long)max_len;

    const int wid  = threadIdx.x >> 5;   // 0..7
    const int lane = threadIdx.x & 31;

    // Each warp owns 4 consecutive rows (channels). Fully unrolled for ILP.
    #pragma unroll
    for (int r = 0; r < 4; ++r) {
        const int c = half * 32 + wid * 4 + r;
        const float* __restrict__ src = src_base + (size_t)c * PT;
        const long long row_idx = out_base + (long long)c * (long long)max_len;
        float* __restrict__ dst = out + row_idx;

        // First 16B-aligned p within this row.
        const int p0 = (int)((4 - (row_idx & 3)) & 3);
        const int nv = (max_len - p0) >> 2;        // # of float4 chunks
        const int ts = p0 + (nv << 2);             // tail start

        // Scalar head (< p0 elements) and tail (< 4 elements), one lane each.
        if (lane < p0) {
            const int p = lane;
            dst[p] = (p < len) ? __ldg(src + p) : 0.0f;
        }
        {
            const int p = ts + lane;
            if (p < max_len)
                dst[p] = (p < len) ? __ldg(src + p) : 0.0f;
        }

        // Vector body: lane k -> chunk at p0 + 4k. Predicated loads; chunks
        // fully inside the pad region issue no loads (pure STG.128 of zeros).
        for (int k = lane; k < nv; k += 32) {
            const int p = p0 + (k << 2);
            float4 v;
            v.x = (p + 0 < len) ? __ldg(src + p + 0) : 0.0f;
            v.y = (p + 1 < len) ? __ldg(src + p + 1) : 0.0f;
            v.z = (p + 2 < len) ? __ldg(src + p + 2) : 0.0f;
            v.w = (p + 3 < len) ? __ldg(src + p + 3) : 0.0f;
            *reinterpret_cast<float4*>(dst + p) = v;
        }
    }
}

extern "C" void kernel_launch(void* const* d_in, const int* in_sizes, int n_in,
                              void* d_out, int out_size)
{
    const float* tensor = (const float*)d_in[0];
    const int*   cps    = (const int*)d_in[1];
    float*       out    = (float*)d_out;

    const int max_len = out_size / (PB * PS * PC);

    dynamic_patching_kernel<<<PB * PS * 2, 256>>>(tensor, cps, out, max_len);
}